// round 14
// baseline (speedup 1.0000x reference)
#include <cuda_runtime.h>

// Problem: CtcBoundaryLossV3 — fused single-launch, SPLIT=4 geometry.
// EXACT R12 source (session best: dur 6.688us) — repeatability check after
// SPLIT=2 regressed to 8.67us with identical ncu kernel time.
// 64 blocks x 512 thr, one frame per thread, smem block reduce (16 warps),
// relaxed per-batch REDs + one acq_rel block ticket (only 64 arrivals),
// packed {rs,ns} accumulators, preloaded text_length.
// Inputs (metadata order):
//   d_in[0] alpha          float32 [B, T]
//   d_in[1] ctc_log_probs  float32 [B, T, V]
//   d_in[2] mask           float32 [B, T]
//   d_in[3] text_length    int32   [B]
// Output: float32 scalar.

#define SPLIT 4
#define MAXB  32
#define NBLK  512                     // threads per block == frames per chunk
#define NWARP (NBLK / 32)             // 16

#define LOG_THR 1.0986122886681098f   // log(3.0)

// Packed per-batch accumulators: [2*b] = float bits (rs), [2*b+1] = int (ns).
__device__ unsigned int g_acc[MAXB * 2];
__device__ unsigned int g_ticket = 0;

__global__ void __launch_bounds__(NBLK)
ctc_fused_kernel(const float* __restrict__ alpha,
                 const float* __restrict__ ctc,
                 const float* __restrict__ mask,
                 const int*   __restrict__ tlen,
                 float* __restrict__ out,
                 int B, int T, int V, int chunkLen) {
    const int bid   = blockIdx.x;           // 0 .. B*SPLIT-1
    const int b     = bid / SPLIT;
    const int chunk = bid % SPLIT;
    const int tid   = threadIdx.x;
    const int lane  = tid & 31;
    const int t     = chunk * chunkLen + tid;

    // Preload text_length per lane (coalesced 64B, L2-hot after block 0;
    // consumed only by the globally-last block's first warp).
    int tl_pre = 1;
    if (lane < B) tl_pre = tlen[lane];

    // ---- Phase 1: one frame per thread ----
    float lsum = 0.0f;
    int   lcnt = 0;
    if (t < T) {
        const size_t idx = (size_t)b * (size_t)T + (size_t)t;
        float a  = alpha[idx];
        float mk = mask[idx];
        float bl = ctc[idx * (size_t)V];    // blank column (index 0)
        lsum = a;
        lcnt = (((1.0f - bl) > LOG_THR) && (mk != 0.0f)) ? 1 : 0;
    }

    // ---- warp reduce ----
    #pragma unroll
    for (int off = 16; off > 0; off >>= 1)
        lsum += __shfl_down_sync(0xFFFFFFFFu, lsum, off);
    lcnt = __reduce_add_sync(0xFFFFFFFFu, lcnt);

    // ---- block reduce (16 warps) ----
    __shared__ float s_sum[NWARP];
    __shared__ int   s_cnt[NWARP];
    __shared__ int   s_amLast;
    const int wid = tid >> 5;
    if (lane == 0) { s_sum[wid] = lsum; s_cnt[wid] = lcnt; }
    if (tid == 0) s_amLast = 0;
    __syncthreads();

    if (tid == 0) {
        float tsum = 0.0f;
        int   tcnt = 0;
        #pragma unroll
        for (int w = 0; w < NWARP; w++) { tsum += s_sum[w]; tcnt += s_cnt[w]; }
        atomicAdd((float*)&g_acc[2 * b], tsum);       // relaxed RED
        atomicAdd((int*)&g_acc[2 * b + 1], tcnt);     // relaxed RED
        // acq_rel ticket: releases our adds, acquires everyone else's.
        unsigned int prev;
        asm volatile("atom.add.acq_rel.gpu.u32 %0, [%1], %2;"
                     : "=r"(prev)
                     : "l"(&g_ticket), "r"(1u)
                     : "memory");
        s_amLast = (prev == gridDim.x - 1u);
    }
    __syncthreads();

    // ---- Phase 2: global-last block finalizes with one warp ----
    if (!s_amLast || tid >= 32) return;

    // Single 8B load per lane covers both rs and ns (one sector pair total).
    float rs = 0.0f;
    int   ns = 0;
    if (lane < B) {
        uint2 p = *(const uint2*)&g_acc[2 * lane];
        rs = __uint_as_float(p.x);
        ns = (int)p.y;
    }
    const int tl = tl_pre;

    // L = min( max_b len_i , max_b text_length )
    int len_i = (lane < B) ? ((ns >= 1) ? ns : 1) : 0;
    int tmx   = (lane < B) ? tl : 0;
    #pragma unroll
    for (int off = 16; off > 0; off >>= 1) {
        len_i = max(len_i, __shfl_xor_sync(0xFFFFFFFFu, len_i, off));
        tmx   = max(tmx,   __shfl_xor_sync(0xFFFFFFFFu, tmx,   off));
    }
    const int L = min(len_i, tmx);

    float ps = 0.0f;
    if (lane < B) {
        int m = min(tl, L);                 // m >= 1 (tl >= 1, L >= 1)
        if (ns >= 1) {
            int k = min(ns, m);
            ps = (float)k * fabsf(rs - 1.0f) + (float)(m - k);
        } else {
            ps = (float)(m - 1);
        }
    }
    #pragma unroll
    for (int off = 16; off > 0; off >>= 1)
        ps += __shfl_xor_sync(0xFFFFFFFFu, ps, off);

    // write result + reset state for next graph replay (one 8B store/lane)
    if (lane < MAXB) *(uint2*)&g_acc[2 * lane] = make_uint2(0u, 0u);
    if (lane == 0) {
        out[0] = ps / (float)B;
        g_ticket = 0;
    }
}

extern "C" void kernel_launch(void* const* d_in, const int* in_sizes, int n_in,
                              void* d_out, int out_size) {
    const float* alpha = (const float*)d_in[0];
    const float* ctc   = (const float*)d_in[1];
    const float* mask  = (const float*)d_in[2];
    const int*   tlen  = (const int*)d_in[3];
    float*       out   = (float*)d_out;

    const int B  = in_sizes[3];
    const int BT = in_sizes[0];
    const int T  = BT / B;
    const int V  = in_sizes[1] / BT;
    const int chunkLen = (T + SPLIT - 1) / SPLIT;   // frames per block

    ctc_fused_kernel<<<B * SPLIT, NBLK>>>(alpha, ctc, mask, tlen, out,
                                          B, T, V, chunkLen);
}

// round 15
// speedup vs baseline: 1.0214x; 1.0214x over previous
#include <cuda_runtime.h>

// Problem: CtcBoundaryLossV3 — fused single-launch, SPLIT=4 geometry.
// R12 structure (session-best mean dur + tied-best ncu kernel time) with one
// local trim: warp-0 lane-parallel block combine instead of thread-0 serial loop.
// 64 blocks x 512 thr, one frame per thread, relaxed per-batch REDs +
// one acq_rel block ticket (64 arrivals), packed {rs,ns} accumulators,
// preloaded text_length.
// Inputs (metadata order):
//   d_in[0] alpha          float32 [B, T]
//   d_in[1] ctc_log_probs  float32 [B, T, V]
//   d_in[2] mask           float32 [B, T]
//   d_in[3] text_length    int32   [B]
// Output: float32 scalar.

#define SPLIT 4
#define MAXB  32
#define NBLK  512                     // threads per block == frames per chunk
#define NWARP (NBLK / 32)             // 16

#define LOG_THR 1.0986122886681098f   // log(3.0)

// Packed per-batch accumulators: [2*b] = float bits (rs), [2*b+1] = int (ns).
__device__ unsigned int g_acc[MAXB * 2];
__device__ unsigned int g_ticket = 0;

__global__ void __launch_bounds__(NBLK)
ctc_fused_kernel(const float* __restrict__ alpha,
                 const float* __restrict__ ctc,
                 const float* __restrict__ mask,
                 const int*   __restrict__ tlen,
                 float* __restrict__ out,
                 int B, int T, int V, int chunkLen) {
    const int bid   = blockIdx.x;           // 0 .. B*SPLIT-1
    const int b     = bid / SPLIT;
    const int chunk = bid % SPLIT;
    const int tid   = threadIdx.x;
    const int lane  = tid & 31;
    const int wid   = tid >> 5;
    const int t     = chunk * chunkLen + tid;

    // Preload text_length per lane (coalesced 64B, L2-hot after block 0;
    // consumed only by the globally-last block's first warp).
    int tl_pre = 1;
    if (lane < B) tl_pre = tlen[lane];

    // ---- Phase 1: one frame per thread ----
    float lsum = 0.0f;
    int   lcnt = 0;
    if (t < T) {
        const size_t idx = (size_t)b * (size_t)T + (size_t)t;
        float a  = alpha[idx];
        float mk = mask[idx];
        float bl = ctc[idx * (size_t)V];    // blank column (index 0)
        lsum = a;
        lcnt = (((1.0f - bl) > LOG_THR) && (mk != 0.0f)) ? 1 : 0;
    }

    // ---- warp reduce ----
    #pragma unroll
    for (int off = 16; off > 0; off >>= 1)
        lsum += __shfl_down_sync(0xFFFFFFFFu, lsum, off);
    lcnt = __reduce_add_sync(0xFFFFFFFFu, lcnt);

    // ---- block reduce (16 warps): leaders deposit, warp 0 combines in parallel ----
    __shared__ float s_sum[NWARP];
    __shared__ int   s_cnt[NWARP];
    __shared__ int   s_amLast;
    if (lane == 0) { s_sum[wid] = lsum; s_cnt[wid] = lcnt; }
    if (tid == 0) s_amLast = 0;
    __syncthreads();

    if (wid == 0) {
        float tsum = (lane < NWARP) ? s_sum[lane] : 0.0f;
        int   tcnt = (lane < NWARP) ? s_cnt[lane] : 0;
        #pragma unroll
        for (int off = 8; off > 0; off >>= 1)
            tsum += __shfl_down_sync(0xFFFFFFFFu, tsum, off);
        tcnt = __reduce_add_sync(0xFFFFFFFFu, tcnt);

        if (lane == 0) {
            atomicAdd((float*)&g_acc[2 * b], tsum);       // relaxed RED
            atomicAdd((int*)&g_acc[2 * b + 1], tcnt);     // relaxed RED
            // acq_rel ticket: releases our adds, acquires everyone else's.
            unsigned int prev;
            asm volatile("atom.add.acq_rel.gpu.u32 %0, [%1], %2;"
                         : "=r"(prev)
                         : "l"(&g_ticket), "r"(1u)
                         : "memory");
            s_amLast = (prev == gridDim.x - 1u);
        }
    }
    __syncthreads();

    // ---- Phase 2: global-last block finalizes with one warp ----
    if (!s_amLast || tid >= 32) return;

    // Single 8B load per lane covers both rs and ns (one sector pair total).
    float rs = 0.0f;
    int   ns = 0;
    if (lane < B) {
        uint2 p = *(const uint2*)&g_acc[2 * lane];
        rs = __uint_as_float(p.x);
        ns = (int)p.y;
    }
    const int tl = tl_pre;

    // L = min( max_b len_i , max_b text_length )
    int len_i = (lane < B) ? ((ns >= 1) ? ns : 1) : 0;
    int tmx   = (lane < B) ? tl : 0;
    #pragma unroll
    for (int off = 16; off > 0; off >>= 1) {
        len_i = max(len_i, __shfl_xor_sync(0xFFFFFFFFu, len_i, off));
        tmx   = max(tmx,   __shfl_xor_sync(0xFFFFFFFFu, tmx,   off));
    }
    const int L = min(len_i, tmx);

    float ps = 0.0f;
    if (lane < B) {
        int m = min(tl, L);                 // m >= 1 (tl >= 1, L >= 1)
        if (ns >= 1) {
            int k = min(ns, m);
            ps = (float)k * fabsf(rs - 1.0f) + (float)(m - k);
        } else {
            ps = (float)(m - 1);
        }
    }
    #pragma unroll
    for (int off = 16; off > 0; off >>= 1)
        ps += __shfl_xor_sync(0xFFFFFFFFu, ps, off);

    // write result + reset state for next graph replay (one 8B store/lane)
    if (lane < MAXB) *(uint2*)&g_acc[2 * lane] = make_uint2(0u, 0u);
    if (lane == 0) {
        out[0] = ps / (float)B;
        g_ticket = 0;
    }
}

extern "C" void kernel_launch(void* const* d_in, const int* in_sizes, int n_in,
                              void* d_out, int out_size) {
    const float* alpha = (const float*)d_in[0];
    const float* ctc   = (const float*)d_in[1];
    const float* mask  = (const float*)d_in[2];
    const int*   tlen  = (const int*)d_in[3];
    float*       out   = (float*)d_out;

    const int B  = in_sizes[3];
    const int BT = in_sizes[0];
    const int T  = BT / B;
    const int V  = in_sizes[1] / BT;
    const int chunkLen = (T + SPLIT - 1) / SPLIT;   // frames per block

    ctc_fused_kernel<<<B * SPLIT, NBLK>>>(alpha, ctc, mask, tlen, out,
                                          B, T, V, chunkLen);
}

// round 16
// speedup vs baseline: 1.3798x; 1.3510x over previous
#include <cuda_runtime.h>

// Problem: CtcBoundaryLossV3 — fused single-launch, vectorized phase 1.
// 64 blocks x 128 thr, FOUR frames per thread (float4 alpha + float4 mask +
// 4 scalar blank loads) -> halves the LSU issue floor vs one-frame-per-thread.
// Tail identical to R15 (best ncu): relaxed per-batch REDs + acq_rel ticket,
// packed {rs,ns} accumulators, preloaded text_length, warp finalize.
// Inputs (metadata order):
//   d_in[0] alpha          float32 [B, T]
//   d_in[1] ctc_log_probs  float32 [B, T, V]
//   d_in[2] mask           float32 [B, T]
//   d_in[3] text_length    int32   [B]
// Output: float32 scalar.

#define SPLIT 4
#define MAXB  32
#define NBLK  128                     // threads per block; 4 frames per thread
#define NWARP (NBLK / 32)             // 4

#define LOG_THR 1.0986122886681098f   // log(3.0)

// Packed per-batch accumulators: [2*b] = float bits (rs), [2*b+1] = int (ns).
__device__ unsigned int g_acc[MAXB * 2];
__device__ unsigned int g_ticket = 0;

__global__ void __launch_bounds__(NBLK)
ctc_fused_kernel(const float* __restrict__ alpha,
                 const float* __restrict__ ctc,
                 const float* __restrict__ mask,
                 const int*   __restrict__ tlen,
                 float* __restrict__ out,
                 int B, int T, int V, int chunkLen) {
    const int bid   = blockIdx.x;           // 0 .. B*SPLIT-1
    const int b     = bid / SPLIT;
    const int chunk = bid % SPLIT;
    const int tid   = threadIdx.x;
    const int lane  = tid & 31;
    const int wid   = tid >> 5;
    const int t0    = chunk * chunkLen;

    // Preload text_length per lane (coalesced 64B, L2-hot after block 0;
    // consumed only by the globally-last block's first warp).
    int tl_pre = 1;
    if (lane < B) tl_pre = tlen[lane];

    // ---- Phase 1: four frames per thread, vectorized ----
    float lsum = 0.0f;
    int   lcnt = 0;
    const size_t rowBase = (size_t)b * (size_t)T;

    const bool vecOK = ((t0 & 3) == 0) && ((chunkLen & 3) == 0) &&
                       (t0 + chunkLen <= T) && (chunkLen == 4 * NBLK);
    if (vecOK) {
        const float4* a4 = (const float4*)(alpha + rowBase + t0);
        const float4* m4 = (const float4*)(mask  + rowBase + t0);
        float4 a = a4[tid];
        float4 m = m4[tid];
        const size_t base = (rowBase + (size_t)(t0 + tid * 4)) * (size_t)V;
        float b0 = ctc[base];
        float b1 = ctc[base +     (size_t)V];
        float b2 = ctc[base + 2 * (size_t)V];
        float b3 = ctc[base + 3 * (size_t)V];
        lsum = (a.x + a.y) + (a.z + a.w);
        lcnt  = (((1.0f - b0) > LOG_THR) && (m.x != 0.0f)) ? 1 : 0;
        lcnt += (((1.0f - b1) > LOG_THR) && (m.y != 0.0f)) ? 1 : 0;
        lcnt += (((1.0f - b2) > LOG_THR) && (m.z != 0.0f)) ? 1 : 0;
        lcnt += (((1.0f - b3) > LOG_THR) && (m.w != 0.0f)) ? 1 : 0;
    } else {
        const int tEnd = min(t0 + chunkLen, T);
        for (int t = t0 + tid; t < tEnd; t += NBLK) {
            const size_t idx = rowBase + (size_t)t;
            float a  = alpha[idx];
            float mk = mask[idx];
            float bl = ctc[idx * (size_t)V];
            lsum += a;
            lcnt += (((1.0f - bl) > LOG_THR) && (mk != 0.0f)) ? 1 : 0;
        }
    }

    // ---- warp reduce ----
    #pragma unroll
    for (int off = 16; off > 0; off >>= 1)
        lsum += __shfl_down_sync(0xFFFFFFFFu, lsum, off);
    lcnt = __reduce_add_sync(0xFFFFFFFFu, lcnt);

    // ---- block reduce (4 warps): leaders deposit, warp 0 combines ----
    __shared__ float s_sum[NWARP];
    __shared__ int   s_cnt[NWARP];
    __shared__ int   s_amLast;
    if (lane == 0) { s_sum[wid] = lsum; s_cnt[wid] = lcnt; }
    if (tid == 0) s_amLast = 0;
    __syncthreads();

    if (wid == 0) {
        float tsum = (lane < NWARP) ? s_sum[lane] : 0.0f;
        int   tcnt = (lane < NWARP) ? s_cnt[lane] : 0;
        #pragma unroll
        for (int off = 2; off > 0; off >>= 1)
            tsum += __shfl_down_sync(0xFFFFFFFFu, tsum, off);
        tcnt = __reduce_add_sync(0xFFFFFFFFu, tcnt);

        if (lane == 0) {
            atomicAdd((float*)&g_acc[2 * b], tsum);       // relaxed RED
            atomicAdd((int*)&g_acc[2 * b + 1], tcnt);     // relaxed RED
            // acq_rel ticket: releases our adds, acquires everyone else's.
            unsigned int prev;
            asm volatile("atom.add.acq_rel.gpu.u32 %0, [%1], %2;"
                         : "=r"(prev)
                         : "l"(&g_ticket), "r"(1u)
                         : "memory");
            s_amLast = (prev == gridDim.x - 1u);
        }
    }
    __syncthreads();

    // ---- Phase 2: global-last block finalizes with one warp ----
    if (!s_amLast || tid >= 32) return;

    // Single 8B load per lane covers both rs and ns (one sector pair total).
    float rs = 0.0f;
    int   ns = 0;
    if (lane < B) {
        uint2 p = *(const uint2*)&g_acc[2 * lane];
        rs = __uint_as_float(p.x);
        ns = (int)p.y;
    }
    const int tl = tl_pre;

    // L = min( max_b len_i , max_b text_length )
    int len_i = (lane < B) ? ((ns >= 1) ? ns : 1) : 0;
    int tmx   = (lane < B) ? tl : 0;
    #pragma unroll
    for (int off = 16; off > 0; off >>= 1) {
        len_i = max(len_i, __shfl_xor_sync(0xFFFFFFFFu, len_i, off));
        tmx   = max(tmx,   __shfl_xor_sync(0xFFFFFFFFu, tmx,   off));
    }
    const int L = min(len_i, tmx);

    float ps = 0.0f;
    if (lane < B) {
        int m = min(tl, L);                 // m >= 1 (tl >= 1, L >= 1)
        if (ns >= 1) {
            int k = min(ns, m);
            ps = (float)k * fabsf(rs - 1.0f) + (float)(m - k);
        } else {
            ps = (float)(m - 1);
        }
    }
    #pragma unroll
    for (int off = 16; off > 0; off >>= 1)
        ps += __shfl_xor_sync(0xFFFFFFFFu, ps, off);

    // write result + reset state for next graph replay (one 8B store/lane)
    if (lane < MAXB) *(uint2*)&g_acc[2 * lane] = make_uint2(0u, 0u);
    if (lane == 0) {
        out[0] = ps / (float)B;
        g_ticket = 0;
    }
}

extern "C" void kernel_launch(void* const* d_in, const int* in_sizes, int n_in,
                              void* d_out, int out_size) {
    const float* alpha = (const float*)d_in[0];
    const float* ctc   = (const float*)d_in[1];
    const float* mask  = (const float*)d_in[2];
    const int*   tlen  = (const int*)d_in[3];
    float*       out   = (float*)d_out;

    const int B  = in_sizes[3];
    const int BT = in_sizes[0];
    const int T  = BT / B;
    const int V  = in_sizes[1] / BT;
    const int chunkLen = (T + SPLIT - 1) / SPLIT;   // frames per block

    ctc_fused_kernel<<<B * SPLIT, NBLK>>>(alpha, ctc, mask, tlen, out,
                                          B, T, V, chunkLen);
}